// round 2
// baseline (speedup 1.0000x reference)
#include <cuda_runtime.h>

#define S 2048
#define DM 512
#define NI 13
#define NC 117    // NI * NP
#define NCP 128   // padded cols
#define TA 128
#define TB 128
#define NCHUNK 16 // S / TA

// ---------------- scratch (static __device__, no allocations) ----------------
__device__ float4 g_xn4[S * DM / 4];       // layernormed x, [s][k]
__device__ float4 g_Wp4[DM * NCP / 4];     // padded W, [k][c]
__device__ float4 g_p4[S * NCP / 4];       // projection p, [s][c]
__device__ float4 g_plin[NI * S];          // {x0, y0, cw, sw} lin channel, [i][a]
__device__ float4 g_pang[NI * S];          // ang channel
__device__ float  g_base[NI * S];          // min + noise_bias, [i][b]
__device__ float  g_partial[NCHUNK * NI * S]; // per-(a-chunk) partial sums

// ---------------- 1) LayerNorm ----------------
__global__ void ln_kernel(const float* __restrict__ h,
                          const float* __restrict__ lw,
                          const float* __restrict__ lb) {
    int s = blockIdx.x, t = threadIdx.x;      // 128 threads, 4 elems each
    const float4* h4 = (const float4*)h;
    float4 v = h4[s * (DM / 4) + t];
    float sum = v.x + v.y + v.z + v.w;
    float sq  = v.x * v.x + v.y * v.y + v.z * v.z + v.w * v.w;
    #pragma unroll
    for (int o = 16; o; o >>= 1) {
        sum += __shfl_xor_sync(0xffffffffu, sum, o);
        sq  += __shfl_xor_sync(0xffffffffu, sq,  o);
    }
    __shared__ float ssum[4], ssq[4];
    int w = t >> 5;
    if ((t & 31) == 0) { ssum[w] = sum; ssq[w] = sq; }
    __syncthreads();
    sum = ssum[0] + ssum[1] + ssum[2] + ssum[3];
    sq  = ssq[0]  + ssq[1]  + ssq[2]  + ssq[3];
    float mu   = sum * (1.0f / DM);
    float var  = sq * (1.0f / DM) - mu * mu;
    float rstd = rsqrtf(var + 1e-5f);
    const float4* lw4 = (const float4*)lw;
    const float4* lb4 = (const float4*)lb;
    float4 wv = lw4[t], bv = lb4[t], o;
    o.x = (v.x - mu) * rstd * wv.x + bv.x;
    o.y = (v.y - mu) * rstd * wv.y + bv.y;
    o.z = (v.z - mu) * rstd * wv.z + bv.z;
    o.w = (v.w - mu) * rstd * wv.w + bv.w;
    g_xn4[s * (DM / 4) + t] = o;
}

// ---------------- 2) pad/transpose W into [k][128] ----------------
__global__ void wprep_kernel(const float* __restrict__ W) {
    int idx = blockIdx.x * 256 + threadIdx.x;   // DM*NCP = 65536
    if (idx >= DM * NCP) return;
    int k = idx >> 7, c = idx & 127;
    ((float*)g_Wp4)[idx] = (c < NC) ? W[k * NC + c] : 0.0f;
}

// ---------------- 3) GEMM: p = xn @ Wp + bias, tile 16 tokens x 128 cols ----
__global__ void gemm_kernel(const float* __restrict__ bias) {
    __shared__ float4 xs4[16][32];              // [m][k/4], k-tile of 128
    const float* xs = (const float*)xs4;
    int t  = threadIdx.x;                        // 128 threads
    int tc = t & 31;                             // col group: cols tc*4..tc*4+3
    int tm = t >> 5;                             // token group: tokens tm*4..tm*4+3
    int s0 = blockIdx.x * 16;
    float acc[4][4];
    #pragma unroll
    for (int m = 0; m < 4; m++)
        #pragma unroll
        for (int c = 0; c < 4; c++) acc[m][c] = 0.0f;

    for (int k0 = 0; k0 < DM; k0 += 128) {
        __syncthreads();
        #pragma unroll
        for (int q = 0; q < 4; q++) {
            int fid = q * 128 + t;
            int m = fid >> 5, kq = fid & 31;
            xs4[m][kq] = g_xn4[(s0 + m) * (DM / 4) + (k0 >> 2) + kq];
        }
        __syncthreads();
        #pragma unroll 4
        for (int k = 0; k < 128; k++) {
            float4 w4 = g_Wp4[(k0 + k) * 32 + tc];
            #pragma unroll
            for (int m = 0; m < 4; m++) {
                float xv = xs[(tm * 4 + m) * 128 + k];
                acc[m][0] = fmaf(xv, w4.x, acc[m][0]);
                acc[m][1] = fmaf(xv, w4.y, acc[m][1]);
                acc[m][2] = fmaf(xv, w4.z, acc[m][2]);
                acc[m][3] = fmaf(xv, w4.w, acc[m][3]);
            }
        }
    }
    int c0 = tc * 4;
    #pragma unroll
    for (int m = 0; m < 4; m++) {
        float4 r;
        r.x = acc[m][0] + ((c0 + 0 < NC) ? bias[c0 + 0] : 0.0f);
        r.y = acc[m][1] + ((c0 + 1 < NC) ? bias[c0 + 1] : 0.0f);
        r.z = acc[m][2] + ((c0 + 2 < NC) ? bias[c0 + 2] : 0.0f);
        r.w = acc[m][3] + ((c0 + 3 < NC) ? bias[c0 + 3] : 0.0f);
        g_p4[(s0 + tm * 4 + m) * 32 + tc] = r;
    }
}

// ---------------- 4) parameter transform -> oscillator states ---------------
__device__ __forceinline__ float softplus_f(float x) {
    return fmaxf(x, 0.0f) + log1pf(expf(-fabsf(x)));
}

__global__ void xform_kernel(const float* __restrict__ minp) {
    int idx = blockIdx.x * 128 + threadIdx.x;   // NI*S = 26624
    if (idx >= NI * S) return;
    int i = idx % NI;
    int s = idx / NI;
    const float* P = ((const float*)g_p4) + s * NCP;
    float p0   = P[ 0 * NI + i];
    float p1   = P[ 1 * NI + i];
    float p2   = P[ 2 * NI + i];
    float p3   = P[ 3 * NI + i];
    float c    = P[ 4 * NI + i];
    float c_th = P[ 5 * NI + i];
    float phi  = P[ 6 * NI + i];
    float phth = P[ 7 * NI + i];
    float p8   = P[ 8 * NI + i];

    // lin channel
    {
        float d  = sqrtf(p1 * p1 + 1e-5f);
        float sp = softplus_f(p0);
        float k  = d * d * 0.25f + sp;
        float om = 0.5f * sqrtf(fmaxf(4.0f * k - d * d, 0.0f));
        float dec = expf(-0.5f * d);
        float so, co; sincosf(om, &so, &co);
        float sp_, cp_; sincosf(phi, &sp_, &cp_);
        g_plin[i * S + s] = make_float4(c * cp_, c * sp_, dec * co, dec * so);
    }
    // ang channel
    {
        float d  = sqrtf(p3 * p3 + 1e-5f);
        float sp = softplus_f(p2);
        float k  = d * d * 0.25f + sp;
        float om = 0.5f * sqrtf(fmaxf(4.0f * k - d * d, 0.0f));
        float dec = expf(-0.5f * d);
        float so, co; sincosf(om, &so, &co);
        float sp_, cp_; sincosf(phth, &sp_, &cp_);
        g_pang[i * S + s] = make_float4(c_th * cp_, c_th * sp_, dec * co, dec * so);
    }
    g_base[i * S + s] = minp[0] + p8;
}

// ---------------- 5) triangular sweep: complex recurrence along b ----------
__global__ void sweep_kernel() {
    int ca = blockIdx.x, cb = blockIdx.y, i = blockIdx.z;
    if (ca > cb) return;
    int lane = threadIdx.x;
    int a0 = ca * TA, b0 = cb * TB;

    float x[8], y[8], cw[8], sw[8], x0v[8], y0v[8];
    int aj[4];
    #pragma unroll
    for (int j = 0; j < 4; j++) {
        int a = a0 + j * 32 + lane;
        aj[j] = a;
        float4 pl = g_plin[i * S + a];
        float4 pa = g_pang[i * S + a];
        x0v[2*j]   = pl.x; y0v[2*j]   = pl.y; cw[2*j]   = pl.z; sw[2*j]   = pl.w;
        x0v[2*j+1] = pa.x; y0v[2*j+1] = pa.y; cw[2*j+1] = pa.z; sw[2*j+1] = pa.w;
    }
    float* pout = g_partial + (ca * NI + i) * S;

    if (ca < cb) {
        // steady tile: init state = z * w^(b0 - a) by exact binary exponentiation
        #pragma unroll
        for (int st = 0; st < 8; st++) {
            unsigned e = (unsigned)(b0 - aj[st >> 1]);
            float rx = 1.0f, ry = 0.0f, bx = cw[st], by = sw[st];
            while (e) {
                if (e & 1u) {
                    float tq = rx * bx - ry * by;
                    ry = rx * by + ry * bx; rx = tq;
                }
                float tq = bx * bx - by * by;
                by = 2.0f * bx * by; bx = tq;
                e >>= 1;
            }
            x[st] = x0v[st] * rx - y0v[st] * ry;
            y[st] = x0v[st] * ry + y0v[st] * rx;
        }
        #pragma unroll 4
        for (int bb = 0; bb < TB; bb++) {
            float ss = ((y[0] + y[1]) + (y[2] + y[3])) + ((y[4] + y[5]) + (y[6] + y[7]));
            #pragma unroll
            for (int o = 16; o; o >>= 1) ss += __shfl_xor_sync(0xffffffffu, ss, o);
            if (lane == 0) pout[b0 + bb] = ss;
            #pragma unroll
            for (int st = 0; st < 8; st++) {
                float nx = x[st] * cw[st] - y[st] * sw[st];
                float ny = x[st] * sw[st] + y[st] * cw[st];
                x[st] = nx; y[st] = ny;
            }
        }
    } else {
        // diagonal tile: ramp in, state born at b == a
        #pragma unroll
        for (int st = 0; st < 8; st++) { x[st] = 0.0f; y[st] = 0.0f; }
        #pragma unroll 4
        for (int bb = 0; bb < TB; bb++) {
            int b = b0 + bb;
            #pragma unroll
            for (int st = 0; st < 8; st++) {
                bool hit = (b == aj[st >> 1]);
                x[st] = hit ? x0v[st] : x[st];
                y[st] = hit ? y0v[st] : y[st];
            }
            float ss = ((y[0] + y[1]) + (y[2] + y[3])) + ((y[4] + y[5]) + (y[6] + y[7]));
            #pragma unroll
            for (int o = 16; o; o >>= 1) ss += __shfl_xor_sync(0xffffffffu, ss, o);
            if (lane == 0) pout[b] = ss;
            #pragma unroll
            for (int st = 0; st < 8; st++) {
                float nx = x[st] * cw[st] - y[st] * sw[st];
                float ny = x[st] * sw[st] + y[st] * cw[st];
                x[st] = nx; y[st] = ny;
            }
        }
    }
}

// ---------------- 6) fold partials + base -> out ----------------
__global__ void reduce_kernel(float* __restrict__ out) {
    int idx = blockIdx.x * 256 + threadIdx.x;   // layout [i][b]
    if (idx >= NI * S) return;
    int i = idx / S;
    int b = idx % S;
    int cb = b >> 7;
    float s = g_base[idx];
    for (int ca = 0; ca <= cb; ca++)
        s += g_partial[(ca * NI + i) * S + b];
    out[idx] = s;
}

// ---------------- launch ----------------
extern "C" void kernel_launch(void* const* d_in, const int* in_sizes, int n_in,
                              void* d_out, int out_size) {
    const float* h    = (const float*)d_in[0];
    const float* mn   = (const float*)d_in[1];
    const float* lw   = (const float*)d_in[2];
    const float* lb   = (const float*)d_in[3];
    const float* W    = (const float*)d_in[4];
    const float* bias = (const float*)d_in[5];
    float* out = (float*)d_out;

    ln_kernel<<<S, 128>>>(h, lw, lb);
    wprep_kernel<<<(DM * NCP + 255) / 256, 256>>>(W);
    gemm_kernel<<<S / 16, 128>>>(bias);
    xform_kernel<<<(NI * S + 127) / 128, 128>>>(mn);
    dim3 g(NCHUNK, NCHUNK, NI);
    sweep_kernel<<<g, 32>>>();
    reduce_kernel<<<(NI * S + 255) / 256, 256>>>(out);
}

// round 3
// speedup vs baseline: 1.9137x; 1.9137x over previous
#include <cuda_runtime.h>

#define S 2048
#define DM 512
#define NI 13
#define NC 117    // NI * NP
#define TA 128
#define TB 128
#define NCHUNK 16 // S / TA

typedef unsigned long long ull;

// ---------------- scratch ----------------
__device__ float4 g_plin[NI * S];          // {x0, y0, cw, sw} lin channel, [i][a]
__device__ float4 g_pang[NI * S];          // ang channel
__device__ float  g_base[NI * S];          // min + noise_bias, [i][b]
__device__ float  g_partial[NCHUNK * NI * S]; // per-(a-chunk) partial sums

// ---------------- packed f32x2 helpers (FFMA2 path, PTX-only) ----------------
__device__ __forceinline__ ull pk2(float lo, float hi) {
    ull r; asm("mov.b64 %0, {%1,%2};" : "=l"(r) : "f"(lo), "f"(hi)); return r;
}
__device__ __forceinline__ void upk2(ull v, float& lo, float& hi) {
    asm("mov.b64 {%0,%1}, %2;" : "=f"(lo), "=f"(hi) : "l"(v));
}
__device__ __forceinline__ ull fma2(ull a, ull b, ull c) {
    ull d; asm("fma.rn.f32x2 %0, %1, %2, %3;" : "=l"(d) : "l"(a), "l"(b), "l"(c)); return d;
}
__device__ __forceinline__ ull mul2(ull a, ull b) {
    ull d; asm("mul.rn.f32x2 %0, %1, %2;" : "=l"(d) : "l"(a), "l"(b)); return d;
}
__device__ __forceinline__ ull add2(ull a, ull b) {
    ull d; asm("add.rn.f32x2 %0, %1, %2;" : "=l"(d) : "l"(a), "l"(b)); return d;
}

__device__ __forceinline__ float softplus_f(float x) {
    return fmaxf(x, 0.0f) + log1pf(expf(-fabsf(x)));
}

// ---------------- 1) fused LN + GEMM + param transform ----------------
// 256 blocks x 128 threads; block handles 8 tokens x 128 cols over K=512.
__global__ __launch_bounds__(128) void gemm_fused(
    const float* __restrict__ h, const float* __restrict__ mn,
    const float* __restrict__ lw, const float* __restrict__ lb,
    const float* __restrict__ W, const float* __restrict__ bias)
{
    __shared__ float xs[8][512];   // 16 KB : layernormed tokens (later reused as p)
    __shared__ float wt[64][128];  // 32 KB : W k-tile

    int t  = threadIdx.x;
    int s0 = blockIdx.x * 8;

    // ---- LayerNorm: 16 threads per row, 8 rows ----
    {
        int r = t >> 4, sub = t & 15;
        const float4* h4 = (const float4*)h;
        float4 v[8];
        float sum = 0.f, sq = 0.f;
        #pragma unroll
        for (int q = 0; q < 8; q++) {
            v[q] = h4[(s0 + r) * (DM / 4) + sub + q * 16];
            sum += v[q].x + v[q].y + v[q].z + v[q].w;
            sq  += v[q].x * v[q].x + v[q].y * v[q].y + v[q].z * v[q].z + v[q].w * v[q].w;
        }
        #pragma unroll
        for (int o = 8; o; o >>= 1) {
            sum += __shfl_xor_sync(0xffffffffu, sum, o);
            sq  += __shfl_xor_sync(0xffffffffu, sq,  o);
        }
        float mu   = sum * (1.0f / DM);
        float var  = sq * (1.0f / DM) - mu * mu;
        float rstd = rsqrtf(var + 1e-5f);
        const float4* lw4 = (const float4*)lw;
        const float4* lb4 = (const float4*)lb;
        #pragma unroll
        for (int q = 0; q < 8; q++) {
            float4 wv = lw4[sub + q * 16], bv = lb4[sub + q * 16], o4;
            o4.x = (v[q].x - mu) * rstd * wv.x + bv.x;
            o4.y = (v[q].y - mu) * rstd * wv.y + bv.y;
            o4.z = (v[q].z - mu) * rstd * wv.z + bv.z;
            o4.w = (v[q].w - mu) * rstd * wv.w + bv.w;
            ((float4*)xs[r])[sub + q * 16] = o4;
        }
    }

    // ---- GEMM: thread owns tokens {tp, tp+4}, cols tc*4..tc*4+3 ----
    int tc = t & 31, tp = t >> 5;
    ull accA0 = pk2(0.f, 0.f), accA1 = accA0, accB0 = accA0, accB1 = accA0;

    for (int k0 = 0; k0 < DM; k0 += 64) {
        __syncthreads();
        // stage W k-tile: 128 threads cover one row of 128 cols (zero-pad 117..127)
        #pragma unroll
        for (int i = 0; i < 64; i++)
            wt[i][t] = (t < NC) ? W[(k0 + i) * NC + t] : 0.0f;
        __syncthreads();
        #pragma unroll 8
        for (int kk = 0; kk < 64; kk++) {
            float xa = xs[tp][k0 + kk];
            float xb = xs[tp + 4][k0 + kk];
            float4 w = *(const float4*)&wt[kk][tc * 4];
            ull xa2 = pk2(xa, xa), xb2 = pk2(xb, xb);
            ull w01 = pk2(w.x, w.y), w23 = pk2(w.z, w.w);
            accA0 = fma2(xa2, w01, accA0);
            accA1 = fma2(xa2, w23, accA1);
            accB0 = fma2(xb2, w01, accB0);
            accB1 = fma2(xb2, w23, accB1);
        }
    }

    __syncthreads();
    // ---- epilogue: p -> smem (reuse xs as ps[8][128]) ----
    float* ps = &xs[0][0];
    {
        float a0, a1, a2, a3, b0v, b1v, b2v, b3v;
        upk2(accA0, a0, a1); upk2(accA1, a2, a3);
        upk2(accB0, b0v, b1v); upk2(accB1, b2v, b3v);
        int c0 = tc * 4;
        float bb0 = (c0 + 0 < NC) ? bias[c0 + 0] : 0.0f;
        float bb1 = (c0 + 1 < NC) ? bias[c0 + 1] : 0.0f;
        float bb2 = (c0 + 2 < NC) ? bias[c0 + 2] : 0.0f;
        float bb3 = (c0 + 3 < NC) ? bias[c0 + 3] : 0.0f;
        ps[tp * 128 + c0 + 0] = a0 + bb0;
        ps[tp * 128 + c0 + 1] = a1 + bb1;
        ps[tp * 128 + c0 + 2] = a2 + bb2;
        ps[tp * 128 + c0 + 3] = a3 + bb3;
        ps[(tp + 4) * 128 + c0 + 0] = b0v + bb0;
        ps[(tp + 4) * 128 + c0 + 1] = b1v + bb1;
        ps[(tp + 4) * 128 + c0 + 2] = b2v + bb2;
        ps[(tp + 4) * 128 + c0 + 3] = b3v + bb3;
    }
    __syncthreads();

    // ---- param transform for this block's 8 tokens x 13 imus ----
    if (t < 8 * NI) {
        int r = t / NI, i = t % NI;
        int s = s0 + r;
        const float* P = ps + r * 128;
        float p0   = P[0 * NI + i];
        float p1   = P[1 * NI + i];
        float p2   = P[2 * NI + i];
        float p3   = P[3 * NI + i];
        float c    = P[4 * NI + i];
        float c_th = P[5 * NI + i];
        float phi  = P[6 * NI + i];
        float phth = P[7 * NI + i];
        float p8   = P[8 * NI + i];
        {
            float d  = sqrtf(p1 * p1 + 1e-5f);
            float sp = softplus_f(p0);
            float k  = d * d * 0.25f + sp;
            float om = 0.5f * sqrtf(fmaxf(4.0f * k - d * d, 0.0f));
            float dec = expf(-0.5f * d);
            float so, co; sincosf(om, &so, &co);
            float sp_, cp_; sincosf(phi, &sp_, &cp_);
            g_plin[i * S + s] = make_float4(c * cp_, c * sp_, dec * co, dec * so);
        }
        {
            float d  = sqrtf(p3 * p3 + 1e-5f);
            float sp = softplus_f(p2);
            float k  = d * d * 0.25f + sp;
            float om = 0.5f * sqrtf(fmaxf(4.0f * k - d * d, 0.0f));
            float dec = expf(-0.5f * d);
            float so, co; sincosf(om, &so, &co);
            float sp_, cp_; sincosf(phth, &sp_, &cp_);
            g_pang[i * S + s] = make_float4(c_th * cp_, c_th * sp_, dec * co, dec * so);
        }
        g_base[i * S + s] = mn[0] + p8;
    }
}

// ---------------- 2) triangular sweep: packed complex recurrence ----------
__global__ __launch_bounds__(32) void sweep_kernel() {
    int ca = blockIdx.x, cb = blockIdx.y, i = blockIdx.z;
    if (ca > cb) return;
    int lane = threadIdx.x;
    int a0 = ca * TA, b0 = cb * TB;

    float x0v[8], y0v[8], cwv[8], swv[8];
    int aj[4];
    #pragma unroll
    for (int j = 0; j < 4; j++) {
        int a = a0 + j * 32 + lane;
        aj[j] = a;
        float4 pl = g_plin[i * S + a];
        float4 pa = g_pang[i * S + a];
        x0v[2*j]   = pl.x; y0v[2*j]   = pl.y; cwv[2*j]   = pl.z; swv[2*j]   = pl.w;
        x0v[2*j+1] = pa.x; y0v[2*j+1] = pa.y; cwv[2*j+1] = pa.z; swv[2*j+1] = pa.w;
    }
    float* pout = g_partial + (ca * NI + i) * S + b0;

    ull X[4], Y[4], CW[4], SW[4], NSW[4];
    #pragma unroll
    for (int j = 0; j < 4; j++) {
        CW[j]  = pk2(cwv[2*j],  cwv[2*j+1]);
        SW[j]  = pk2(swv[2*j],  swv[2*j+1]);
        NSW[j] = pk2(-swv[2*j], -swv[2*j+1]);
    }

    if (ca < cb) {
        // init state = z * w^(b0 - a) via exact binary exponentiation (scalar)
        float xi[8], yi[8];
        #pragma unroll
        for (int st = 0; st < 8; st++) {
            unsigned e = (unsigned)(b0 - aj[st >> 1]);
            float rx = 1.0f, ry = 0.0f, bx = cwv[st], by = swv[st];
            while (e) {
                if (e & 1u) {
                    float tq = rx * bx - ry * by;
                    ry = rx * by + ry * bx; rx = tq;
                }
                float tq = bx * bx - by * by;
                by = 2.0f * bx * by; bx = tq;
                e >>= 1;
            }
            xi[st] = x0v[st] * rx - y0v[st] * ry;
            yi[st] = x0v[st] * ry + y0v[st] * rx;
        }
        #pragma unroll
        for (int j = 0; j < 4; j++) { X[j] = pk2(xi[2*j], xi[2*j+1]); Y[j] = pk2(yi[2*j], yi[2*j+1]); }

        #pragma unroll 4
        for (int bb = 0; bb < TB; bb++) {
            ull s2 = add2(add2(Y[0], Y[1]), add2(Y[2], Y[3]));
            float slo, shi; upk2(s2, slo, shi);
            float ss = slo + shi;
            #pragma unroll
            for (int o = 16; o; o >>= 1) ss += __shfl_xor_sync(0xffffffffu, ss, o);
            if (lane == 0) pout[bb] = ss;
            #pragma unroll
            for (int j = 0; j < 4; j++) {
                ull t1 = mul2(Y[j], NSW[j]);
                ull t2 = mul2(X[j], SW[j]);
                X[j] = fma2(X[j], CW[j], t1);
                Y[j] = fma2(Y[j], CW[j], t2);
            }
        }
    } else {
        ull X0[4], Y0[4];
        #pragma unroll
        for (int j = 0; j < 4; j++) {
            X0[j] = pk2(x0v[2*j], x0v[2*j+1]);
            Y0[j] = pk2(y0v[2*j], y0v[2*j+1]);
            X[j] = pk2(0.f, 0.f); Y[j] = X[j];
        }
        #pragma unroll 4
        for (int bb = 0; bb < TB; bb++) {
            int b = b0 + bb;
            #pragma unroll
            for (int j = 0; j < 4; j++) {
                if (b == aj[j]) { X[j] = X0[j]; Y[j] = Y0[j]; }
            }
            ull s2 = add2(add2(Y[0], Y[1]), add2(Y[2], Y[3]));
            float slo, shi; upk2(s2, slo, shi);
            float ss = slo + shi;
            #pragma unroll
            for (int o = 16; o; o >>= 1) ss += __shfl_xor_sync(0xffffffffu, ss, o);
            if (lane == 0) pout[bb] = ss;
            #pragma unroll
            for (int j = 0; j < 4; j++) {
                ull t1 = mul2(Y[j], NSW[j]);
                ull t2 = mul2(X[j], SW[j]);
                X[j] = fma2(X[j], CW[j], t1);
                Y[j] = fma2(Y[j], CW[j], t2);
            }
        }
    }
}

// ---------------- 3) fold partials + base -> out ----------------
__global__ void reduce_kernel(float* __restrict__ out) {
    int idx = blockIdx.x * 256 + threadIdx.x;   // layout [i][b]
    if (idx >= NI * S) return;
    int i = idx / S;
    int b = idx % S;
    int cb = b >> 7;
    float s = g_base[idx];
    for (int ca = 0; ca <= cb; ca++)
        s += g_partial[(ca * NI + i) * S + b];
    out[idx] = s;
}

// ---------------- launch ----------------
extern "C" void kernel_launch(void* const* d_in, const int* in_sizes, int n_in,
                              void* d_out, int out_size) {
    const float* h    = (const float*)d_in[0];
    const float* mn   = (const float*)d_in[1];
    const float* lw   = (const float*)d_in[2];
    const float* lb   = (const float*)d_in[3];
    const float* W    = (const float*)d_in[4];
    const float* bias = (const float*)d_in[5];
    float* out = (float*)d_out;

    gemm_fused<<<S / 8, 128>>>(h, mn, lw, lb, W, bias);
    dim3 g(NCHUNK, NCHUNK, NI);
    sweep_kernel<<<g, 32>>>();
    reduce_kernel<<<(NI * S + 255) / 256, 256>>>(out);
}